// round 1
// baseline (speedup 1.0000x reference)
#include <cuda_runtime.h>

#define BB 4
#define NN 4096
#define MM 4096
#define DD 128
#define KK 64
#define GC 20
#define NCELL (GC*GC)
#define CAND_CAP 1024
#define TIE_CAP 256

// scratch (static device globals — allowed)
__device__ int    g_cellCnt[BB*NCELL];
__device__ int    g_cellStart[BB*(NCELL+1)];
__device__ int    g_cursor[BB*NCELL];
__device__ float2 g_slocs[BB*NN];
__device__ int    g_sid[BB*NN];
__device__ int    g_idx[BB*MM*KK];
__device__ float  g_p[BB*MM*KK];
__device__ float  g_eu[BB*MM];
__device__ float  g_ev[BB*NN];
__device__ float  g_cs[BB*NN];

__global__ void k_init() {
    int i = blockIdx.x*256 + threadIdx.x;
    if (i < BB*NN) { g_ev[i] = 1.0f; g_cs[i] = 0.0f; }
    if (i < BB*NCELL) g_cellCnt[i] = 0;
}

__global__ void k_count(const float2* __restrict__ slocs) {
    int i = blockIdx.x*256 + threadIdx.x;
    if (i >= BB*NN) return;
    float2 p = slocs[i];
    int b = i / NN;
    int cx = min(GC-1, max(0, (int)(p.x * GC)));
    int cy = min(GC-1, max(0, (int)(p.y * GC)));
    atomicAdd(&g_cellCnt[b*NCELL + cy*GC + cx], 1);
}

__global__ void k_scan() {
    __shared__ int sc[512];
    int b = blockIdx.x, t = threadIdx.x;
    int v = (t < NCELL) ? g_cellCnt[b*NCELL + t] : 0;
    sc[t] = v;
    __syncthreads();
    for (int off = 1; off < 512; off <<= 1) {
        int x = (t >= off) ? sc[t-off] : 0;
        __syncthreads();
        sc[t] += x;
        __syncthreads();
    }
    if (t < NCELL) {
        int excl = sc[t] - v;
        g_cellStart[b*(NCELL+1) + t] = excl;
        g_cursor[b*NCELL + t] = excl;
    }
    if (t == NCELL-1) g_cellStart[b*(NCELL+1) + NCELL] = sc[t];
}

__global__ void k_fill(const float2* __restrict__ slocs) {
    int i = blockIdx.x*256 + threadIdx.x;
    if (i >= BB*NN) return;
    float2 p = slocs[i];
    int b = i / NN, n = i - b*NN;
    int cx = min(GC-1, max(0, (int)(p.x * GC)));
    int cy = min(GC-1, max(0, (int)(p.y * GC)));
    int pos = atomicAdd(&g_cursor[b*NCELL + cy*GC + cx], 1);
    g_slocs[b*NN + pos] = p;
    g_sid[b*NN + pos] = n;
}

// one block per target row: gather candidates (grid-pruned), histogram-select 64 smallest dist
__global__ void __launch_bounds__(128) k_topk(const float2* __restrict__ tlocs) {
    __shared__ float s_d[CAND_CAP];
    __shared__ int   s_j[CAND_CAP];
    __shared__ float s_td[TIE_CAP];
    __shared__ int   s_tj[TIE_CAP];
    __shared__ int   s_hist[256];
    __shared__ int   s_cnt, s_ncov, s_nsel, s_ntie, s_tb, s_r;

    int m = blockIdx.x, b = blockIdx.y;
    int row = b*MM + m;
    int tid = threadIdx.x;
    if (tid == 0) { s_cnt = 0; s_ncov = 0; }
    __syncthreads();

    float2 t = tlocs[row];
    int cx = min(GC-1, max(0, (int)(t.x*GC)));
    int cy = min(GC-1, max(0, (int)(t.y*GC)));
    int x0 = max(cx-3, 0), x1 = min(cx+3, GC-1);
    int y0 = max(cy-3, 0), y1 = min(cy+3, GC-1);
    int wid = tid >> 5, lane = tid & 31;
    int ncov = 0;
    const int* cs = &g_cellStart[b*(NCELL+1)];
    for (int yy = y0 + wid; yy <= y1; yy += 4) {
        int lo = cs[yy*GC + x0];
        int hi = cs[yy*GC + x1 + 1];
        for (int j = lo + lane; j < hi; j += 32) {
            float2 s = g_slocs[b*NN + j];
            float dx = t.x - s.x, dy = t.y - s.y;
            float d = fmaf(dy, dy, dx*dx);
            if (d < 0.04f) {
                int p = atomicAdd(&s_cnt, 1);
                if (p < CAND_CAP) { s_d[p] = d; s_j[p] = j; }
                if (d < 0.0225f) ncov++;   // inside guaranteed-covered radius 0.15
            }
        }
    }
    if (ncov) atomicAdd(&s_ncov, ncov);
    __syncthreads();
    int cnt = min(s_cnt, CAND_CAP);
    bool fb = (s_ncov < KK) || (s_cnt > CAND_CAP);   // exactness guard
    __syncthreads();
    if (fb) {
        // brute-force rescan over all sources (rare: boundary targets)
        if (tid == 0) s_cnt = 0;
        __syncthreads();
        for (int j = tid; j < NN; j += 128) {
            float2 s = g_slocs[b*NN + j];
            float dx = t.x - s.x, dy = t.y - s.y;
            float d = fmaf(dy, dy, dx*dx);
            if (d < 0.04f) {
                int p = atomicAdd(&s_cnt, 1);
                if (p < CAND_CAP) { s_d[p] = d; s_j[p] = j; }
            }
        }
        __syncthreads();
        cnt = min(s_cnt, CAND_CAP);
    }

    const float kDen = 0.01000001f;   // EPSILON + 1e-8 in f32
    int*   oid = &g_idx[(size_t)row*KK];
    float* op  = &g_p[(size_t)row*KK];

    if (cnt <= KK) {
        for (int j = tid; j < KK; j += 128) {
            if (j < cnt) { oid[j] = g_sid[b*NN + s_j[j]]; op[j] = expf(-s_d[j]/kDen); }
            else         { oid[j] = 0;                    op[j] = 0.0f; }
        }
        return;
    }

    // histogram select: dist^2 uniform on [0,0.04) -> 256 equi-probable bins
    s_hist[tid] = 0; s_hist[tid+128] = 0;
    if (tid == 0) { s_nsel = 0; s_ntie = 0; }
    __syncthreads();
    for (int j = tid; j < cnt; j += 128)
        atomicAdd(&s_hist[min(255, (int)(s_d[j]*6400.0f))], 1);
    __syncthreads();
    if (tid == 0) {
        int c = 0, tb = 0;
        for (; tb < 256; tb++) { int h = s_hist[tb]; if (c + h >= KK) break; c += h; }
        s_tb = tb; s_r = KK - c;
    }
    __syncthreads();
    int tb = s_tb, r = s_r;
    for (int j = tid; j < cnt; j += 128) {
        int bn = min(255, (int)(s_d[j]*6400.0f));
        if (bn < tb) {
            int p = atomicAdd(&s_nsel, 1);
            oid[p] = g_sid[b*NN + s_j[j]];
            op[p]  = expf(-s_d[j]/kDen);
        } else if (bn == tb) {
            int p = atomicAdd(&s_ntie, 1);
            if (p < TIE_CAP) { s_td[p] = s_d[j]; s_tj[p] = s_j[j]; }
        }
    }
    __syncthreads();
    if (tid == 0) {
        int base = s_nsel;              // == KK - r
        int nt = min(s_ntie, TIE_CAP);  // expected ~2 entries in boundary bin
        for (int k2 = 0; k2 < r; k2++) {
            float best = 1e30f; int bj = 0;
            for (int j2 = 0; j2 < nt; j2++) if (s_td[j2] < best) { best = s_td[j2]; bj = j2; }
            oid[base+k2] = g_sid[b*NN + s_tj[bj]];
            op[base+k2]  = expf(-best/kDen);
            s_td[bj] = 1e30f;
        }
    }
}

// one warp per row: eu = 1/sum(p*ev[idx]); scatter p*eu into column sums
__global__ void k_u_scatter() {
    int gt = blockIdx.x*256 + threadIdx.x;
    int w = gt >> 5;
    if (w >= BB*MM) return;
    int lane = gt & 31;
    int b = w >> 12;   // w / MM
    const int*   ri = &g_idx[(size_t)w*KK];
    const float* rp = &g_p[(size_t)w*KK];
    int   i0 = ri[lane],     i1 = ri[lane+32];
    float p0 = rp[lane],     p1 = rp[lane+32];
    const float* ev = &g_ev[b*NN];
    float s = p0*ev[i0] + p1*ev[i1];
    #pragma unroll
    for (int o = 16; o; o >>= 1) s += __shfl_xor_sync(0xffffffffu, s, o);
    float eu = (s > 0.0f) ? (1.0f / s) : 0.0f;
    if (lane == 0) g_eu[w] = eu;
    float* csum = &g_cs[b*NN];
    float w0 = p0*eu, w1 = p1*eu;
    if (w0 != 0.0f) atomicAdd(&csum[i0], w0);
    if (w1 != 0.0f) atomicAdd(&csum[i1], w1);
}

__global__ void k_v_update() {
    int i = blockIdx.x*256 + threadIdx.x;
    if (i >= BB*NN) return;
    float c = g_cs[i];
    g_ev[i] = (c > 0.0f) ? (1.0f / c) : 0.0f;
    g_cs[i] = 0.0f;
}

// out[row, d] = sum_j (p_j * eu_row * ev[idx_j]) * feats[idx_j, d]
__global__ void __launch_bounds__(128) k_out(const float* __restrict__ feats,
                                             float* __restrict__ out) {
    __shared__ float s_w[KK];
    __shared__ int   s_i[KK];
    int m = blockIdx.x, b = blockIdx.y;
    int row = b*MM + m;
    int tid = threadIdx.x;
    if (tid < KK) {
        int   i = g_idx[(size_t)row*KK + tid];
        float p = g_p[(size_t)row*KK + tid];
        float w = p * g_eu[row] * g_ev[b*NN + i];
        s_w[tid] = w; s_i[tid] = i;
    }
    __syncthreads();
    const float* fb = feats + (size_t)b*NN*DD;
    float acc = 0.0f;
    #pragma unroll 16
    for (int j = 0; j < KK; j++)
        acc = fmaf(s_w[j], fb[(size_t)s_i[j]*DD + tid], acc);
    out[(size_t)row*DD + tid] = acc;
}

extern "C" void kernel_launch(void* const* d_in, const int* in_sizes, int n_in,
                              void* d_out, int out_size) {
    const float*  feats = (const float*)d_in[0];
    const float2* slocs = (const float2*)d_in[1];
    const float2* tlocs = (const float2*)d_in[2];
    float* out = (float*)d_out;

    int nb = (BB*NN + 255) / 256;
    k_init<<<nb, 256>>>();
    k_count<<<nb, 256>>>(slocs);
    k_scan<<<BB, 512>>>();
    k_fill<<<nb, 256>>>(slocs);

    dim3 g(MM, BB);
    k_topk<<<g, 128>>>(tlocs);

    for (int it = 0; it < 8; it++) {
        k_u_scatter<<<(BB*MM*32)/256, 256>>>();
        k_v_update<<<nb, 256>>>();
    }
    k_out<<<g, 128>>>(feats, out);
}

// round 3
// speedup vs baseline: 1.1491x; 1.1491x over previous
#include <cuda_runtime.h>

#define BB 4
#define NN 4096
#define MM 4096
#define DD 128
#define KK 64
#define GC 20
#define NCELL (GC*GC)
#define TIE_CAP 96
#define NBLK 128
#define NTHR 1024
#define NWARP (NBLK*(NTHR/32))           // 4096 warps
#define RPW ((BB*MM)/NWARP)              // 4 rows per warp
#define FULLM 0xffffffffu

// scratch (static device globals)
__device__ int    g_cellCnt[BB*NCELL];
__device__ int    g_cellStart[BB*(NCELL+1)];
__device__ int    g_cursor[BB*NCELL];
__device__ float2 g_slocs[BB*NN];
__device__ int    g_sid[BB*NN];
__device__ int    g_idx[BB*MM*KK];
__device__ float  g_p[BB*MM*KK];
__device__ float  g_cs[3][BB*NN];
__device__ unsigned g_barcnt;
__device__ unsigned g_bargen;

__global__ void k_init() {
    int i = blockIdx.x*256 + threadIdx.x;
    if (i < BB*NN) { g_cs[0][i] = 1.0f; g_cs[1][i] = 0.0f; g_cs[2][i] = 0.0f; }
    if (i < BB*NCELL) g_cellCnt[i] = 0;
    if (i == 0) { g_barcnt = 0; g_bargen = 0; }
}

__global__ void k_count(const float2* __restrict__ slocs) {
    int i = blockIdx.x*256 + threadIdx.x;
    if (i >= BB*NN) return;
    float2 p = slocs[i];
    int b = i / NN;
    int cx = min(GC-1, max(0, (int)(p.x * GC)));
    int cy = min(GC-1, max(0, (int)(p.y * GC)));
    atomicAdd(&g_cellCnt[b*NCELL + cy*GC + cx], 1);
}

__global__ void k_scan() {
    __shared__ int sc[512];
    int b = blockIdx.x, t = threadIdx.x;
    int v = (t < NCELL) ? g_cellCnt[b*NCELL + t] : 0;
    sc[t] = v;
    __syncthreads();
    for (int off = 1; off < 512; off <<= 1) {
        int x = (t >= off) ? sc[t-off] : 0;
        __syncthreads();
        sc[t] += x;
        __syncthreads();
    }
    if (t < NCELL) {
        int excl = sc[t] - v;
        g_cellStart[b*(NCELL+1) + t] = excl;
        g_cursor[b*NCELL + t] = excl;
    }
    if (t == NCELL-1) g_cellStart[b*(NCELL+1) + NCELL] = sc[t];
}

__global__ void k_fill(const float2* __restrict__ slocs) {
    int i = blockIdx.x*256 + threadIdx.x;
    if (i >= BB*NN) return;
    float2 p = slocs[i];
    int b = i / NN, n = i - b*NN;
    int cx = min(GC-1, max(0, (int)(p.x * GC)));
    int cy = min(GC-1, max(0, (int)(p.y * GC)));
    int pos = atomicAdd(&g_cursor[b*NCELL + cy*GC + cx], 1);
    g_slocs[b*NN + pos] = p;
    g_sid[b*NN + pos] = n;
}

// ---------------------------------------------------------------------------
// top-k: one warp per target row, 2-pass (histogram, then re-scan & emit).
// ---------------------------------------------------------------------------
#define TK_WARPS 8
__global__ void __launch_bounds__(TK_WARPS*32) k_topk(const float2* __restrict__ tlocs) {
    __shared__ int   s_hist[TK_WARPS][256];
    __shared__ float s_td[TK_WARPS][TIE_CAP];
    __shared__ int   s_tj[TK_WARPS][TIE_CAP];

    int warp = threadIdx.x >> 5, lane = threadIdx.x & 31;
    int row = blockIdx.x*TK_WARPS + warp;
    int b = row >> 12;
    unsigned lmask = (1u << lane) - 1u;

    float2 t = tlocs[row];
    int cx = min(GC-1, max(0, (int)(t.x*GC)));
    int cy = min(GC-1, max(0, (int)(t.y*GC)));
    int x0 = max(cx-3, 0), x1 = min(cx+3, GC-1);
    int y0 = max(cy-3, 0), y1 = min(cy+3, GC-1);
    const int* cs = &g_cellStart[b*(NCELL+1)];
    const float2* sl = &g_slocs[b*NN];

    #pragma unroll
    for (int i = 0; i < 8; i++) s_hist[warp][lane*8+i] = 0;
    __syncwarp();

    // ---- pass 1: histogram over box candidates ----
    int cnt = 0, ncov = 0;
    for (int yy = y0; yy <= y1; yy++) {
        int lo = cs[yy*GC + x0];
        int hi = cs[yy*GC + x1 + 1];
        for (int base = lo; base < hi; base += 32) {
            int j = base + lane;
            float d = 1e9f;
            if (j < hi) {
                float2 s = sl[j];
                float dx = t.x - s.x, dy = t.y - s.y;
                d = fmaf(dy, dy, dx*dx);
            }
            bool hit = d < 0.04f;
            if (hit) atomicAdd(&s_hist[warp][min(255, (int)(d*6400.0f))], 1);
            cnt  += __popc(__ballot_sync(FULLM, hit));
            ncov += __popc(__ballot_sync(FULLM, d < 0.0225f));
        }
    }

    bool fullscan = (ncov < KK);
    if (fullscan) {
        #pragma unroll
        for (int i = 0; i < 8; i++) s_hist[warp][lane*8+i] = 0;
        __syncwarp();
        cnt = 0;
        for (int base = 0; base < NN; base += 32) {
            int j = base + lane;
            float2 s = sl[j];
            float dx = t.x - s.x, dy = t.y - s.y;
            float d = fmaf(dy, dy, dx*dx);
            bool hit = d < 0.04f;
            if (hit) atomicAdd(&s_hist[warp][min(255, (int)(d*6400.0f))], 1);
            cnt += __popc(__ballot_sync(FULLM, hit));
        }
    }
    __syncwarp();

    const float kInv = 99.9999f;    // 1/(EPSILON+1e-8)
    int*   oid = &g_idx[(size_t)row*KK];
    float* op  = &g_p[(size_t)row*KK];

    if (cnt <= KK) {
        int pos = 0;
        if (!fullscan) {
            for (int yy = y0; yy <= y1; yy++) {
                int lo = cs[yy*GC + x0];
                int hi = cs[yy*GC + x1 + 1];
                for (int base = lo; base < hi; base += 32) {
                    int j = base + lane;
                    float d = 1e9f;
                    if (j < hi) {
                        float2 s = sl[j];
                        float dx = t.x - s.x, dy = t.y - s.y;
                        d = fmaf(dy, dy, dx*dx);
                    }
                    bool hit = d < 0.04f;
                    unsigned bm = __ballot_sync(FULLM, hit);
                    int p = pos + __popc(bm & lmask);
                    if (hit && p < KK) { oid[p] = g_sid[b*NN + j]; op[p] = __expf(-d*kInv); }
                    pos += __popc(bm);
                }
            }
        } else {
            for (int base = 0; base < NN; base += 32) {
                int j = base + lane;
                float2 s = sl[j];
                float dx = t.x - s.x, dy = t.y - s.y;
                float d = fmaf(dy, dy, dx*dx);
                bool hit = d < 0.04f;
                unsigned bm = __ballot_sync(FULLM, hit);
                int p = pos + __popc(bm & lmask);
                if (hit && p < KK) { oid[p] = g_sid[b*NN + j]; op[p] = __expf(-d*kInv); }
                pos += __popc(bm);
            }
        }
        for (int p = pos + lane; p < KK; p += 32) { oid[p] = 0; op[p] = 0.0f; }
        return;
    }

    // ---- threshold bin via warp-parallel prefix over 256 bins ----
    int h[8]; int part = 0;
    #pragma unroll
    for (int i = 0; i < 8; i++) { h[i] = s_hist[warp][lane*8+i]; part += h[i]; }
    int inc = part;
    #pragma unroll
    for (int off = 1; off < 32; off <<= 1) {
        int y = __shfl_up_sync(FULLM, inc, off);
        if (lane >= off) inc += y;
    }
    int exc = inc - part;
    int tb = -1, r = 0;
    if (exc < KK && KK <= inc) {
        int c = exc;
        #pragma unroll
        for (int i = 0; i < 8; i++) {
            if (tb < 0) {
                if (c + h[i] >= KK) { tb = lane*8 + i; r = KK - c; }
                else c += h[i];
            }
        }
    }
    int srcl = __ffs(__ballot_sync(FULLM, tb >= 0)) - 1;
    tb = __shfl_sync(FULLM, tb, srcl);
    r  = __shfl_sync(FULLM, r,  srcl);

    // ---- pass 2: re-scan, emit below-threshold, collect ties ----
    int pos = 0, ntie = 0;
    if (!fullscan) {
        for (int yy = y0; yy <= y1; yy++) {
            int lo = cs[yy*GC + x0];
            int hi = cs[yy*GC + x1 + 1];
            for (int base = lo; base < hi; base += 32) {
                int j = base + lane;
                float d = 1e9f;
                if (j < hi) {
                    float2 s = sl[j];
                    float dx = t.x - s.x, dy = t.y - s.y;
                    d = fmaf(dy, dy, dx*dx);
                }
                int bn = (d < 0.04f) ? min(255, (int)(d*6400.0f)) : 256;
                bool sel = bn < tb, tie = bn == tb;
                unsigned bs = __ballot_sync(FULLM, sel);
                int p = pos + __popc(bs & lmask);
                if (sel) { oid[p] = g_sid[b*NN + j]; op[p] = __expf(-d*kInv); }
                pos += __popc(bs);
                unsigned bt = __ballot_sync(FULLM, tie);
                int q = ntie + __popc(bt & lmask);
                if (tie && q < TIE_CAP) { s_td[warp][q] = d; s_tj[warp][q] = j; }
                ntie += __popc(bt);
            }
        }
    } else {
        for (int base = 0; base < NN; base += 32) {
            int j = base + lane;
            float2 s = sl[j];
            float dx = t.x - s.x, dy = t.y - s.y;
            float d = fmaf(dy, dy, dx*dx);
            int bn = (d < 0.04f) ? min(255, (int)(d*6400.0f)) : 256;
            bool sel = bn < tb, tie = bn == tb;
            unsigned bs = __ballot_sync(FULLM, sel);
            int p = pos + __popc(bs & lmask);
            if (sel) { oid[p] = g_sid[b*NN + j]; op[p] = __expf(-d*kInv); }
            pos += __popc(bs);
            unsigned bt = __ballot_sync(FULLM, tie);
            int q = ntie + __popc(bt & lmask);
            if (tie && q < TIE_CAP) { s_td[warp][q] = d; s_tj[warp][q] = j; }
            ntie += __popc(bt);
        }
    }
    __syncwarp();
    if (lane == 0) {
        int nt = min(ntie, TIE_CAP);
        int rr = min(r, nt);
        for (int k2 = 0; k2 < rr; k2++) {
            float best = 1e30f; int bj = 0;
            for (int j2 = 0; j2 < nt; j2++)
                if (s_td[warp][j2] < best) { best = s_td[warp][j2]; bj = j2; }
            oid[pos+k2] = g_sid[b*NN + s_tj[warp][bj]];
            op[pos+k2]  = __expf(-best*kInv);
            s_td[warp][bj] = 1e30f;
        }
        for (int k2 = rr; k2 < r; k2++) { oid[pos+k2] = 0; op[pos+k2] = 0.0f; }
    }
}

// ---------------------------------------------------------------------------
// persistent: 8 Sinkhorn iterations (register-cached idx/p, 1 barrier/iter,
// 3-buffer colsum rotation) + fused output GEMM.
// ---------------------------------------------------------------------------
__device__ __forceinline__ unsigned ld_acq(const unsigned* p) {
    unsigned v;
    asm volatile("ld.acquire.gpu.u32 %0, [%1];" : "=r"(v) : "l"(p) : "memory");
    return v;
}
__device__ __forceinline__ void st_rel(unsigned* p, unsigned v) {
    asm volatile("st.release.gpu.u32 [%0], %1;" :: "l"(p), "r"(v) : "memory");
}

__device__ __forceinline__ void gridbar() {
    __syncthreads();
    if (threadIdx.x == 0) {
        unsigned g = ld_acq(&g_bargen);
        __threadfence();
        if (atomicAdd(&g_barcnt, 1u) == NBLK - 1) {
            g_barcnt = 0;
            st_rel(&g_bargen, g + 1);
        } else {
            while (ld_acq(&g_bargen) == g) { __nanosleep(20); }
        }
    }
    __syncthreads();
}

__global__ void __launch_bounds__(NTHR, 1) k_sink(const float* __restrict__ feats,
                                                  float* __restrict__ out) {
    int lane = threadIdx.x & 31;
    int gw = blockIdx.x*(NTHR/32) + (threadIdx.x >> 5);
    int gid = blockIdx.x*NTHR + threadIdx.x;

    int   i0[RPW], i1[RPW];
    float p0[RPW], p1[RPW], eu[RPW];
    int   bofs[RPW];

    #pragma unroll
    for (int k = 0; k < RPW; k++) {
        int r = gw*RPW + k;
        bofs[k] = (r >> 12) * NN;
        const int*   ri = &g_idx[(size_t)r*KK];
        const float* rp = &g_p[(size_t)r*KK];
        i0[k] = ri[lane];     i1[k] = ri[lane+32];
        p0[k] = rp[lane];     p1[k] = rp[lane+32];
    }

    #pragma unroll 1
    for (int t = 0; t < 8; t++) {
        const float* crd = g_cs[t % 3];
        float*       cwr = g_cs[(t+1) % 3];
        float*       czr = g_cs[(t+2) % 3];
        if (gid < BB*NN) czr[gid] = 0.0f;
        #pragma unroll
        for (int k = 0; k < RPW; k++) {
            float c0 = __ldcg(&crd[bofs[k] + i0[k]]);
            float c1 = __ldcg(&crd[bofs[k] + i1[k]]);
            float s = ((c0 > 0.0f) ? p0[k]/c0 : 0.0f)
                    + ((c1 > 0.0f) ? p1[k]/c1 : 0.0f);
            #pragma unroll
            for (int o = 16; o; o >>= 1) s += __shfl_xor_sync(FULLM, s, o);
            float e = (s > 0.0f) ? 1.0f/s : 0.0f;
            eu[k] = e;
            float w0 = p0[k]*e, w1 = p1[k]*e;
            if (w0 != 0.0f) atomicAdd(&cwr[bofs[k] + i0[k]], w0);
            if (w1 != 0.0f) atomicAdd(&cwr[bofs[k] + i1[k]], w1);
        }
        gridbar();
    }

    // ---- output: out[r, :] = sum_j p_j*eu*ev[i_j] * feats[i_j, :] ----
    const float* evbuf = g_cs[2];   // cwr of final iteration (t=7)
    #pragma unroll 1
    for (int k = 0; k < RPW; k++) {
        int r = gw*RPW + k;
        const float* fb = feats + (size_t)bofs[k]*DD;
        float c0 = __ldcg(&evbuf[bofs[k] + i0[k]]);
        float c1 = __ldcg(&evbuf[bofs[k] + i1[k]]);
        float w0 = p0[k]*eu[k]*((c0 > 0.0f) ? 1.0f/c0 : 0.0f);
        float w1 = p1[k]*eu[k]*((c1 > 0.0f) ? 1.0f/c1 : 0.0f);
        float4 acc = make_float4(0.f, 0.f, 0.f, 0.f);
        #pragma unroll 16
        for (int j = 0; j < KK; j++) {
            int src = j & 31;
            float wj = __shfl_sync(FULLM, (j < 32) ? w0 : w1, src);
            int   ij = __shfl_sync(FULLM, (j < 32) ? i0[k] : i1[k], src);
            const float4* f4 = (const float4*)(fb + (size_t)ij*DD);
            float4 v = f4[lane];
            acc.x = fmaf(wj, v.x, acc.x);
            acc.y = fmaf(wj, v.y, acc.y);
            acc.z = fmaf(wj, v.z, acc.z);
            acc.w = fmaf(wj, v.w, acc.w);
        }
        ((float4*)(out + (size_t)r*DD))[lane] = acc;
    }
}

extern "C" void kernel_launch(void* const* d_in, const int* in_sizes, int n_in,
                              void* d_out, int out_size) {
    const float*  feats = (const float*)d_in[0];
    const float2* slocs = (const float2*)d_in[1];
    const float2* tlocs = (const float2*)d_in[2];
    float* out = (float*)d_out;

    int nb = (BB*NN + 255) / 256;
    k_init<<<nb, 256>>>();
    k_count<<<nb, 256>>>(slocs);
    k_scan<<<BB, 512>>>();
    k_fill<<<nb, 256>>>(slocs);
    k_topk<<<(BB*MM)/TK_WARPS, TK_WARPS*32>>>(tlocs);
    k_sink<<<NBLK, NTHR>>>(feats, out);
}